// round 15
// baseline (speedup 1.0000x reference)
#include <cuda_runtime.h>
#include <cstdint>

#define MAX_NODES 65536

// Scratch (allocation-free: __device__ globals)
__device__ float  g_M[2 * 256];     // folded matrix M[r][k] = sum_i W2a[r][i] * W1[i][k]
__device__ float  g_c[2];           // folded bias c[r] = W2a[r]@W1b + b2[r]
__device__ float2 g_pu[MAX_NODES];  // per-node src contribution (2 classes)
__device__ float2 g_pv[MAX_NODES];  // per-node dst contribution

static __device__ __forceinline__ void pdl_trigger() {
    asm volatile("griddepcontrol.launch_dependents;");
}
static __device__ __forceinline__ void pdl_wait() {
    asm volatile("griddepcontrol.wait;" ::: "memory");
}

// ---------------------------------------------------------------------------
// Kernel 1: fold W2a @ W1 -> M [2 x 256], c = W2a@W1b + b2.
//   R8 empirical-best: one warp per output; lanes split K, butterfly reduce.
//   Triggers dependents at entry so node/edge preambles overlap.
// ---------------------------------------------------------------------------
__global__ void __launch_bounds__(256)
k_fold(const float* __restrict__ W1w, const float* __restrict__ W1b,
       const float* __restrict__ W2w, const float* __restrict__ W2b)
{
    pdl_trigger();
    const int gw   = (blockIdx.x * blockDim.x + threadIdx.x) >> 5;
    const int lane = threadIdx.x & 31;

    if (gw < 512) {
        const int r = gw >> 8;
        const int k = gw & 255;
        float acc = 0.0f;
        #pragma unroll
        for (int j = 0; j < 8; j++) {
            const int i = j * 32 + lane;
            acc = fmaf(__ldg(&W2w[r * 288 + i]), __ldg(&W1w[i * 256 + k]), acc);
        }
        #pragma unroll
        for (int o = 16; o > 0; o >>= 1)
            acc += __shfl_xor_sync(0xFFFFFFFFu, acc, o);
        if (lane == 0) g_M[r * 256 + k] = acc;
    } else if (gw < 514) {
        const int r = gw - 512;
        float acc = 0.0f;
        #pragma unroll
        for (int j = 0; j < 8; j++) {
            const int i = j * 32 + lane;
            acc = fmaf(__ldg(&W2w[r * 288 + i]), __ldg(&W1b[i]), acc);
        }
        #pragma unroll
        for (int o = 16; o > 0; o >>= 1)
            acc += __shfl_xor_sync(0xFFFFFFFFu, acc, o);
        if (lane == 0) g_c[r] = acc + W2b[r];
    }
}

// ---------------------------------------------------------------------------
// Kernel 2: per-node transform, 4 threads/node, PDL preamble:
//   prefetch this thread's quarter of h into registers BEFORE waiting on fold,
//   so the 25.6 MB h-stream overlaps k_fold. Then load M (L1-cached) and FMA.
// ---------------------------------------------------------------------------
__global__ void __launch_bounds__(512)
k_node(const float* __restrict__ h, int n_nodes)
{
    pdl_trigger();                           // let k_edge's e-stream start too
    const int t   = threadIdx.x;
    const int sub = t & 3;                   // quarter of the 128-dim row
    const int n   = blockIdx.x * 128 + (t >> 2);

    float4 x[8];                             // preamble: independent h loads
    if (n < n_nodes) {
        const float4* __restrict__ hv = (const float4*)(h + (size_t)n * 128 + sub * 32);
        #pragma unroll
        for (int q = 0; q < 8; q++) x[q] = hv[q];
    }

    pdl_wait();                              // fold's g_M/g_c now visible
    if (n >= n_nodes) return;

    const float4* __restrict__ gm = (const float4*)g_M;
    const int mq = sub * 8;
    float pu0 = 0.f, pu1 = 0.f, pv0 = 0.f, pv1 = 0.f;
    #pragma unroll
    for (int q = 0; q < 8; q++) {
        const float4 a  = __ldg(&gm[mq + q]);        // M[0][  0..127] quarter
        const float4 b  = __ldg(&gm[32 + mq + q]);   // M[0][128..255]
        const float4 cc = __ldg(&gm[64 + mq + q]);   // M[1][  0..127]
        const float4 d  = __ldg(&gm[96 + mq + q]);   // M[1][128..255]
        pu0 = fmaf(x[q].x, a.x, pu0);  pu0 = fmaf(x[q].y, a.y, pu0);
        pu0 = fmaf(x[q].z, a.z, pu0);  pu0 = fmaf(x[q].w, a.w, pu0);
        pv0 = fmaf(x[q].x, b.x, pv0);  pv0 = fmaf(x[q].y, b.y, pv0);
        pv0 = fmaf(x[q].z, b.z, pv0);  pv0 = fmaf(x[q].w, b.w, pv0);
        pu1 = fmaf(x[q].x, cc.x, pu1); pu1 = fmaf(x[q].y, cc.y, pu1);
        pu1 = fmaf(x[q].z, cc.z, pu1); pu1 = fmaf(x[q].w, cc.w, pu1);
        pv1 = fmaf(x[q].x, d.x, pv1);  pv1 = fmaf(x[q].y, d.y, pv1);
        pv1 = fmaf(x[q].z, d.z, pv1);  pv1 = fmaf(x[q].w, d.w, pv1);
    }
    // reduce across the 4 sub-lanes of this node
    pu0 += __shfl_xor_sync(0xFFFFFFFFu, pu0, 1);
    pu1 += __shfl_xor_sync(0xFFFFFFFFu, pu1, 1);
    pv0 += __shfl_xor_sync(0xFFFFFFFFu, pv0, 1);
    pv1 += __shfl_xor_sync(0xFFFFFFFFu, pv1, 1);
    pu0 += __shfl_xor_sync(0xFFFFFFFFu, pu0, 2);
    pu1 += __shfl_xor_sync(0xFFFFFFFFu, pu1, 2);
    pv0 += __shfl_xor_sync(0xFFFFFFFFu, pv0, 2);
    pv1 += __shfl_xor_sync(0xFFFFFFFFu, pv1, 2);

    if (sub == 0) {
        g_pu[n] = make_float2(pu0, pu1);
        g_pv[n] = make_float2(pv0, pv1);
    }
}

// ---------------------------------------------------------------------------
// Kernel 3: fused edge stage, 4 threads/edge, PDL preamble:
//   entire 82 MB e-dot + index loads run BEFORE waiting on k_node; only the
//   pu/pv/c gathers sit behind the dependency.
// ---------------------------------------------------------------------------
__global__ void __launch_bounds__(512)
k_edge(const int* __restrict__ src, const int* __restrict__ dst,
       const float* __restrict__ e, const float* __restrict__ W2w,
       float2* __restrict__ out, int n_edges)
{
    const int t    = threadIdx.x;
    const int sub  = t & 3;                 // quarter of the 32-dim e row
    const int eloc = t >> 2;                // 0..127 edges per CTA
    const int edge = blockIdx.x * 128 + eloc;

    float w0[8], w1[8];
    #pragma unroll
    for (int q = 0; q < 8; q++) {
        w0[q] = W2w[256 + sub * 8 + q];
        w1[q] = W2w[288 + 256 + sub * 8 + q];
    }

    float s0 = 0.f, s1 = 0.f;
    int su = 0, dv = 0;
    if (edge < n_edges) {
        const float4* __restrict__ ep = (const float4*)(e + (size_t)edge * 32 + sub * 8);
        const float4 v0 = ep[0];
        const float4 v1 = ep[1];
        if (sub == 0) { su = src[edge]; dv = dst[edge]; }
        s0 = fmaf(w0[0], v0.x, s0); s1 = fmaf(w1[0], v0.x, s1);
        s0 = fmaf(w0[1], v0.y, s0); s1 = fmaf(w1[1], v0.y, s1);
        s0 = fmaf(w0[2], v0.z, s0); s1 = fmaf(w1[2], v0.z, s1);
        s0 = fmaf(w0[3], v0.w, s0); s1 = fmaf(w1[3], v0.w, s1);
        s0 = fmaf(w0[4], v1.x, s0); s1 = fmaf(w1[4], v1.x, s1);
        s0 = fmaf(w0[5], v1.y, s0); s1 = fmaf(w1[5], v1.y, s1);
        s0 = fmaf(w0[6], v1.z, s0); s1 = fmaf(w1[6], v1.z, s1);
        s0 = fmaf(w0[7], v1.w, s0); s1 = fmaf(w1[7], v1.w, s1);
    }
    s0 += __shfl_xor_sync(0xFFFFFFFFu, s0, 1);
    s1 += __shfl_xor_sync(0xFFFFFFFFu, s1, 1);
    s0 += __shfl_xor_sync(0xFFFFFFFFu, s0, 2);
    s1 += __shfl_xor_sync(0xFFFFFFFFu, s1, 2);

    pdl_wait();                              // node's tables now visible

    if (sub == 0 && edge < n_edges) {
        const float2 a = g_pu[su];           // L2-resident gathers
        const float2 b = g_pv[dv];
        out[edge] = make_float2(s0 + a.x + b.x + g_c[0],
                                s1 + a.y + b.y + g_c[1]);
    }
}

// ---------------------------------------------------------------------------
extern "C" void kernel_launch(void* const* d_in, const int* in_sizes, int n_in,
                              void* d_out, int out_size)
{
    const float* h   = (const float*)d_in[0];
    const int*   src = (const int*)d_in[1];
    const int*   dst = (const int*)d_in[2];
    const float* e   = (const float*)d_in[3];
    const float* W1w = (const float*)d_in[4];
    const float* W1b = (const float*)d_in[5];
    const float* W2w = (const float*)d_in[6];
    const float* W2b = (const float*)d_in[7];
    float2* out = (float2*)d_out;

    const int n_nodes = in_sizes[0] / 128;
    const int n_edges = in_sizes[1];

    k_fold<<<65, 256>>>(W1w, W1b, W2w, W2b);

    cudaLaunchAttribute attr[1];
    attr[0].id = cudaLaunchAttributeProgrammaticStreamSerialization;
    attr[0].val.programmaticStreamSerializationAllowed = 1;

    cudaLaunchConfig_t cfg = {};
    cfg.blockDim = dim3(512, 1, 1);
    cfg.stream   = 0;
    cfg.attrs    = attr;
    cfg.numAttrs = 1;

    cfg.gridDim = dim3((unsigned)((n_nodes + 127) / 128), 1, 1);
    cudaLaunchKernelEx(&cfg, k_node, h, n_nodes);

    cfg.gridDim = dim3((unsigned)((n_edges + 127) / 128), 1, 1);
    cudaLaunchKernelEx(&cfg, k_edge, src, dst, e, W2w, out, n_edges);
}